// round 1
// baseline (speedup 1.0000x reference)
#include <cuda_runtime.h>
#include <math.h>

// ---------------------------------------------------------------------------
// Problem constants
//   inp [16,1,64,64,64] -> block0 (gated) -> [16,20,33,33,33]
//                       -> block1 (gated) -> [16,20,18,18,18]
//                       -> block2 (none)  -> mean -> [16,20] -> fc -> [16,2]
// Block2+mean is collapsed: mean(conv2(x)) = (1/1000) * S[b,ci,t] . K2[co,ci,t]
// where S[b,ci,t] = sum over 10^3 output points of strided samples of act1.
// ---------------------------------------------------------------------------

__device__ float g_B[3*125];           // radial basis [3][125]
__device__ float g_K0[1*125*24];       // synthesized conv0 weights [ci][tap][co_pad24]
__device__ float g_K1[20*125*24];      // conv1 weights [ci][tap][co_pad24]
__device__ float g_K2[20*125*20];      // conv2 weights [ci][tap][co20]
__device__ float g_act0[16*20*33*33*33];
__device__ float g_act1[16*20*18*18*18];
__device__ float g_S[16*20*125];

// ---------------------------------------------------------------------------
// Radial basis: B_j(r) on 5^3 grid, L2-normalized per shell (double precision).
// ---------------------------------------------------------------------------
__global__ void k_basis(float* __restrict__ B) {
    __shared__ double vals[3][125];
    int t = threadIdx.x;
    if (t < 125) {
        int dz = t / 25 - 2;
        int dy = (t / 5) % 5 - 2;
        int dx = t % 5 - 2;
        double r = sqrt((double)(dz*dz + dy*dy + dx*dx));
        for (int j = 0; j < 3; j++) {
            double d = (r - (double)j) / 0.6;
            vals[j][t] = exp(-0.5 * d * d);
        }
    }
    __syncthreads();
    if (t < 3) {
        double s = 0.0;
        for (int i = 0; i < 125; i++) s += vals[t][i] * vals[t][i];
        double inv = 1.0 / sqrt(s);
        for (int i = 0; i < 125; i++) B[t*125 + i] = (float)(vals[t][i] * inv);
    }
}

// ---------------------------------------------------------------------------
// Kernel synthesis: K[ci][tap][co] = sum_j W[co,ci,j] * B[j][tap]; co zero-padded.
// ---------------------------------------------------------------------------
__global__ void k_synth(const float* __restrict__ W, const float* __restrict__ B,
                        float* __restrict__ K, int CIN, int COUTC, int CP) {
    int idx = blockIdx.x * blockDim.x + threadIdx.x;
    int total = CIN * 125 * CP;
    if (idx >= total) return;
    int co = idx % CP;
    int t  = (idx / CP) % 125;
    int ci = idx / (CP * 125);
    float v = 0.f;
    if (co < COUTC) {
        for (int j = 0; j < 3; j++)
            v += W[(co*CIN + ci)*3 + j] * B[j*125 + t];
    }
    K[idx] = v;
}

// ---------------------------------------------------------------------------
// Gated stride-2 size-5 conv3d, register-row-blocked direct conv.
//   Each thread: P consecutive x outputs * C out-channels in registers.
//   Per (tz,ty): load one input row (2P+3 floats) to regs, reuse for all tx.
//   Epilogue: stage 23 conv channels in smem, apply capsule gating -> 20 ch.
// ---------------------------------------------------------------------------
template<int CIN, int COUTC, int CP, int C, int P,
         int TZ, int TY, int TX, int DIN, int DOUT>
__global__ void __launch_bounds__((TZ*TY)*(TX/P)*(CP/C), 1)
conv_gated_kernel(const float* __restrict__ in, const float* __restrict__ Kw,
                  float* __restrict__ out)
{
    constexpr int XC   = TX / P;
    constexpr int ROWS = TZ * TY;
    constexpr int CG   = CP / C;
    constexpr int NT   = ROWS * XC * CG;
    constexpr int IZ = 2*TZ + 3, IY = 2*TY + 3, IX = 2*TX + 3;
    constexpr int IN_ELEMS = IZ * IY * IX;
    constexpr int IN_PAD   = (IN_ELEMS + 3) & ~3;   // 16B-align weight region
    constexpr int NPT = TZ * TY * TX;
    constexpr int TYC = (DOUT + TY - 1) / TY;

    extern __shared__ float smem[];
    float* sIn = smem;            // [IN_PAD]
    float* sW  = smem + IN_PAD;   // [125*CP]
    float* sY  = smem;            // [NPT*CP] (overlaps; used only after mainloop)

    const int tid   = threadIdx.x;
    const int b     = blockIdx.y;
    const int tilez = blockIdx.x / TYC;
    const int tiley = blockIdx.x % TYC;
    const int oz0 = tilez * TZ, oy0 = tiley * TY;

    const int cg  = tid / (ROWS * XC);
    const int rem = tid % (ROWS * XC);
    const int row = rem / XC;
    const int xc  = rem % XC;
    const int rz = row / TY, ry = row % TY;
    const bool valid = (oz0 + rz < DOUT) && (oy0 + ry < DOUT);
    const int xbase = xc * P;

    float acc[P][C];
#pragma unroll
    for (int p = 0; p < P; p++)
#pragma unroll
        for (int c = 0; c < C; c++) acc[p][c] = 0.f;

    for (int ci = 0; ci < CIN; ci++) {
        // cooperative load of input tile (zero-padded halo)
        const float* gin = in + (long)(b*CIN + ci) * (DIN*DIN*DIN);
        for (int idx = tid; idx < IN_ELEMS; idx += NT) {
            int iz = idx / (IY*IX);
            int r2 = idx % (IY*IX);
            int iy = r2 / IX;
            int ix = r2 % IX;
            int gz = 2*oz0 - 3 + iz;
            int gy = 2*oy0 - 3 + iy;
            int gx = ix - 3;
            float v = 0.f;
            if ((unsigned)gz < (unsigned)DIN && (unsigned)gy < (unsigned)DIN &&
                (unsigned)gx < (unsigned)DIN)
                v = gin[(gz*DIN + gy)*DIN + gx];
            sIn[idx] = v;
        }
        // cooperative load of synthesized weights [125][CP]
        const float* gw = Kw + ci * 125 * CP;
        for (int idx = tid; idx < 125*CP; idx += NT) sW[idx] = gw[idx];
        __syncthreads();

        if (valid) {
            for (int tz = 0; tz < 5; tz++) {
                for (int ty = 0; ty < 5; ty++) {
                    float rowv[2*P + 3];
                    const float* rp =
                        &sIn[((2*rz + tz)*IY + (2*ry + ty))*IX + 2*xbase];
#pragma unroll
                    for (int k = 0; k < 2*P + 3; k++) rowv[k] = rp[k];
#pragma unroll
                    for (int tx = 0; tx < 5; tx++) {
                        float wv[C];
                        const float4* wp = reinterpret_cast<const float4*>(
                            &sW[(tz*25 + ty*5 + tx)*CP + cg*C]);
#pragma unroll
                        for (int c4 = 0; c4 < C/4; c4++) {
                            float4 f = wp[c4];
                            wv[4*c4+0] = f.x; wv[4*c4+1] = f.y;
                            wv[4*c4+2] = f.z; wv[4*c4+3] = f.w;
                        }
#pragma unroll
                        for (int p = 0; p < P; p++) {
                            float xv = rowv[2*p + tx];
#pragma unroll
                            for (int c = 0; c < C; c++)
                                acc[p][c] = fmaf(xv, wv[c], acc[p][c]);
                        }
                    }
                }
            }
        }
        __syncthreads();
    }

    // ---- epilogue: stage conv outputs, gate, write 20 channels ----
    if (valid) {
#pragma unroll
        for (int p = 0; p < P; p++)
#pragma unroll
            for (int c = 0; c < C; c++)
                sY[(row*TX + xbase + p)*CP + cg*C + c] = acc[p][c];
    }
    __syncthreads();

    // replace gate channels 20..22 with their sigmoid, once per point
    for (int idx = tid; idx < NPT*3; idx += NT) {
        int pt = idx % NPT;
        int k  = idx / NPT;
        int rr = pt / TX;
        int rzz = rr / TY, ryy = rr % TY;
        if (oz0 + rzz < DOUT && oy0 + ryy < DOUT) {
            float g = sY[pt*CP + 20 + k];
            sY[pt*CP + 20 + k] = 1.f / (1.f + expf(-g));
        }
    }
    __syncthreads();

    float* gout = out + (long)b * 20 * (DOUT*DOUT*DOUT);
    for (int idx = tid; idx < NPT*20; idx += NT) {
        int pt = idx % NPT;      // x fastest -> coalesced stores
        int oc = idx / NPT;
        int ox  = pt % TX;
        int rr  = pt / TX;
        int ryy = rr % TY;
        int rzz = rr / TY;
        int oz = oz0 + rzz, oy = oy0 + ryy;
        if (oz < DOUT && oy < DOUT && ox < DOUT) {
            float y = sY[pt*CP + oc];
            float v;
            if (oc < 5) {
                v = fmaxf(y, 0.f);
            } else {
                int gi = (oc < 8) ? 0 : ((oc < 13) ? 1 : 2);
                v = y * sY[pt*CP + 20 + gi];
            }
            gout[(oc*DOUT + oz)*(DOUT*DOUT) + oy*DOUT + ox] = v;
        }
    }
}

// ---------------------------------------------------------------------------
// S[b,ci,t] = sum over 10^3 stride-2 sampled points of act1 (pad 3) per tap t.
// One block per (b,ci): 5832-float tile in smem, 125 taps across threads.
// ---------------------------------------------------------------------------
__global__ void kS_kernel(const float* __restrict__ act, float* __restrict__ S) {
    __shared__ float s[5832];
    int ci = blockIdx.x;
    int b  = blockIdx.y;
    int tid = threadIdx.x;
    const float* p = act + (long)(b*20 + ci) * 5832;
    for (int i = tid; i < 5832; i += 128) s[i] = p[i];
    __syncthreads();
    if (tid < 125) {
        int tz = tid / 25, ty = (tid / 5) % 5, tx = tid % 5;
        float sum = 0.f;
        for (int oz = 0; oz < 10; oz++) {
            int z = 2*oz + tz - 3;
            if ((unsigned)z >= 18u) continue;
            for (int oy = 0; oy < 10; oy++) {
                int y = 2*oy + ty - 3;
                if ((unsigned)y >= 18u) continue;
                int base = (z*18 + y)*18;
                for (int ox = 0; ox < 10; ox++) {
                    int x = 2*ox + tx - 3;
                    if ((unsigned)x >= 18u) continue;
                    sum += s[base + x];
                }
            }
        }
        S[(b*20 + ci)*125 + tid] = sum;
    }
}

// ---------------------------------------------------------------------------
// Head: pooled[b,co] = (1/1000) * sum_i S[b,i] * K2[i,co]; then fc1(relu), fc2.
// ---------------------------------------------------------------------------
__global__ void head_kernel(const float* __restrict__ S, const float* __restrict__ K2,
                            const float* __restrict__ fc1w, const float* __restrict__ fc1b,
                            const float* __restrict__ fc2w, const float* __restrict__ fc2b,
                            float* __restrict__ out) {
    __shared__ float pooled[16*20];
    __shared__ float h1[16*50];
    int t = threadIdx.x;  // 320 threads
    {
        int b  = t / 20;
        int co = t % 20;
        float a0 = 0.f, a1 = 0.f;
        const float* sp = S + b*2500;
        for (int i = 0; i < 2500; i += 2) {
            a0 = fmaf(sp[i    ], K2[(i    )*20 + co], a0);
            a1 = fmaf(sp[i + 1], K2[(i + 1)*20 + co], a1);
        }
        pooled[b*20 + co] = (a0 + a1) * (1.0f/1000.0f);
    }
    __syncthreads();
    for (int idx = t; idx < 16*50; idx += 320) {
        int b = idx / 50, j = idx % 50;
        float a = fc1b[j];
        for (int k = 0; k < 20; k++)
            a = fmaf(pooled[b*20 + k], fc1w[j*20 + k], a);
        h1[b*50 + j] = fmaxf(a, 0.f);
    }
    __syncthreads();
    if (t < 32) {
        int b = t / 2, o = t % 2;
        float a = fc2b[o];
        for (int k = 0; k < 50; k++)
            a = fmaf(h1[b*50 + k], fc2w[o*50 + k], a);
        out[b*2 + o] = a;
    }
}

// ---------------------------------------------------------------------------
// Host launcher
// ---------------------------------------------------------------------------
extern "C" void kernel_launch(void* const* d_in, const int* in_sizes, int n_in,
                              void* d_out, int out_size) {
    const float* inp  = (const float*)d_in[0];
    const float* W0   = (const float*)d_in[1];
    const float* W1   = (const float*)d_in[2];
    const float* W2   = (const float*)d_in[3];
    const float* fc1w = (const float*)d_in[4];
    const float* fc1b = (const float*)d_in[5];
    const float* fc2w = (const float*)d_in[6];
    const float* fc2b = (const float*)d_in[7];
    float* out = (float*)d_out;

    float *gB, *gK0, *gK1, *gK2, *gA0, *gA1, *gS;
    cudaGetSymbolAddress((void**)&gB,  g_B);
    cudaGetSymbolAddress((void**)&gK0, g_K0);
    cudaGetSymbolAddress((void**)&gK1, g_K1);
    cudaGetSymbolAddress((void**)&gK2, g_K2);
    cudaGetSymbolAddress((void**)&gA0, g_act0);
    cudaGetSymbolAddress((void**)&gA1, g_act1);
    cudaGetSymbolAddress((void**)&gS,  g_S);

    k_basis<<<1, 128>>>(gB);
    k_synth<<<(1*125*24 + 255)/256,  256>>>(W0, gB, gK0, 1, 23, 24);
    k_synth<<<(20*125*24 + 255)/256, 256>>>(W1, gB, gK1, 20, 23, 24);
    k_synth<<<(20*125*20 + 255)/256, 256>>>(W2, gB, gK2, 20, 20, 20);

    // ---- conv0: [16,1,64^3] -> gated [16,20,33^3] ----
    // tile (6,6,33), P=11, C=12: NT = 36*3*2 = 216 threads
    {
        constexpr int IN_PAD = ((15*15*69) + 3) & ~3;           // 15528
        constexpr int SMEM = ((6*6*33)*24 > IN_PAD + 125*24
                              ? (6*6*33)*24 : IN_PAD + 125*24) * 4;  // 114048
        auto k = conv_gated_kernel<1, 23, 24, 12, 11, 6, 6, 33, 64, 33>;
        cudaFuncSetAttribute(k, cudaFuncAttributeMaxDynamicSharedMemorySize, SMEM);
        k<<<dim3(6*6, 16), 216, SMEM>>>(inp, gK0, gA0);
    }

    // ---- conv1: [16,20,33^3] -> gated [16,20,18^3] ----
    // tile (6,6,18), P=6, C=12: NT = 36*3*2 = 216 threads
    {
        constexpr int IN_PAD = ((15*15*39) + 3) & ~3;           // 8776
        constexpr int SMEM = ((6*6*18)*24 > IN_PAD + 125*24
                              ? (6*6*18)*24 : IN_PAD + 125*24) * 4;  // 62208
        auto k = conv_gated_kernel<20, 23, 24, 12, 6, 6, 6, 18, 33, 18>;
        cudaFuncSetAttribute(k, cudaFuncAttributeMaxDynamicSharedMemorySize, SMEM);
        k<<<dim3(3*3, 16), 216, SMEM>>>(gA0, gK1, gA1);
    }

    // ---- block2 collapsed: strided sums S, then head ----
    kS_kernel<<<dim3(20, 16), 128>>>(gA1, gS);
    head_kernel<<<1, 320>>>(gS, gK2, fc1w, fc1b, fc2w, fc2b, out);
}